// round 4
// baseline (speedup 1.0000x reference)
#include <cuda_runtime.h>

// out[m][n] = C[m][n] * D[n];  8192 x 8192 f32, row-major.
// 8192 blocks x 256 threads x 8 float4 = 16,777,216 float4s (single pass).
// 8 front-batched reads then 8 stores per thread: long same-direction DRAM
// bursts (fewer R/W turnarounds), MLP=8 per warp.
// STRIDE = 8192*256 = 2,097,152 float4s (32 MB), multiple of NR4=2048, so
// the D scale is invariant across all 8 elements -> loaded once.

static constexpr int NR4    = 2048;          // float4s per row
static constexpr int STRIDE = 8192 * 256;    // 2,097,152

__global__ __launch_bounds__(256)
void colscale_kernel(const float4* __restrict__ C,
                     const float4* __restrict__ D,
                     float4* __restrict__ out)
{
    const int i = blockIdx.x * 256 + threadIdx.x;   // 0 .. 2,097,151

    const float4 d = __ldg(&D[i & (NR4 - 1)]);

    float4 c[8];
    #pragma unroll
    for (int k = 0; k < 8; k++)
        c[k] = C[i + k * STRIDE];

    #pragma unroll
    for (int k = 0; k < 8; k++) {
        c[k].x *= d.x; c[k].y *= d.y; c[k].z *= d.z; c[k].w *= d.w;
    }

    #pragma unroll
    for (int k = 0; k < 8; k++)
        out[i + k * STRIDE] = c[k];
}

extern "C" void kernel_launch(void* const* d_in, const int* in_sizes, int n_in,
                              void* d_out, int out_size)
{
    const float4* C = (const float4*)d_in[0];
    const float4* D = (const float4*)d_in[1];
    float4* out     = (float4*)d_out;

    colscale_kernel<<<8192, 256>>>(C, D, out);
}

// round 5
// speedup vs baseline: 1.0047x; 1.0047x over previous
#include <cuda_runtime.h>

// out[m][n] = C[m][n] * D[n];  8192 x 8192 f32, row-major.
// Best-known structure (R3): 16384 blocks x 256 threads x 4 float4, loads
// spaced 64 MB apart (spans all HBM channels / both L2 dies), D loaded once
// (stride is a multiple of NR4). Isolated change vs R3: stores use __stcs
// (evict-first) so zero-reuse output lines don't compete for L2 residency.

static constexpr int NR4    = 2048;                 // float4s per row
static constexpr int STRIDE = 16384 * 256;          // grid * block = 4,194,304

__global__ __launch_bounds__(256, 6)
void colscale_kernel(const float4* __restrict__ C,
                     const float4* __restrict__ D,
                     float4* __restrict__ out)
{
    const int i = blockIdx.x * 256 + threadIdx.x;   // 0 .. 4,194,303

    // STRIDE % NR4 == 0 -> column index identical across the 4 elements.
    const float4 d = __ldg(&D[i & (NR4 - 1)]);

    const int i0 = i;
    const int i1 = i + STRIDE;
    const int i2 = i + 2 * STRIDE;
    const int i3 = i + 3 * STRIDE;

    // Front-batched loads (MLP=4), 64 MB apart.
    float4 c0 = C[i0];
    float4 c1 = C[i1];
    float4 c2 = C[i2];
    float4 c3 = C[i3];

    c0.x *= d.x; c0.y *= d.y; c0.z *= d.z; c0.w *= d.w;
    c1.x *= d.x; c1.y *= d.y; c1.z *= d.z; c1.w *= d.w;
    c2.x *= d.x; c2.y *= d.y; c2.z *= d.z; c2.w *= d.w;
    c3.x *= d.x; c3.y *= d.y; c3.z *= d.z; c3.w *= d.w;

    __stcs(&out[i0], c0);
    __stcs(&out[i1], c1);
    __stcs(&out[i2], c2);
    __stcs(&out[i3], c3);
}

extern "C" void kernel_launch(void* const* d_in, const int* in_sizes, int n_in,
                              void* d_out, int out_size)
{
    const float4* C = (const float4*)d_in[0];
    const float4* D = (const float4*)d_in[1];
    float4* out     = (float4*)d_out;

    colscale_kernel<<<16384, 256>>>(C, D, out);
}